// round 1
// baseline (speedup 1.0000x reference)
#include <cuda_runtime.h>
#include <cuda_bf16.h>
#include <math.h>

// ---------------------------------------------------------------------------
// AtomicRouteConv — restructured GNN pipeline
//   Stage1: scatter raw x_src rows + degree -> dense GEMM for h_mid_agg
//   Stage2: dense GEMMs for K,V,Q -> per-edge dot -> global softmax -> scatter
// ---------------------------------------------------------------------------

#define C      128
#define NM     50000
#define ND     50000
#define NS     50000
#define NE1    640000
#define NE2    640000
#define INV_SQRT_C 0.08838834764831843f   // 1/sqrt(128)

// ---------------- scratch (static device allocations; no cudaMalloc) -------
__device__ float g_smid[NM * C];     // scatter-sum of x_src rows by mid
__device__ float g_deg [NM];         // edge count per mid node (stage 1)
__device__ float g_h   [NM * C];     // h_mid_agg
__device__ float g_K   [NM * C];
__device__ float g_V   [NM * C];
__device__ float g_Q   [ND * C];
__device__ float g_esc [NE2];        // exp(score) per edge
__device__ float g_sum [1];
__device__ float g_inv [1];
__device__ int   g_idx64;            // 1 if edge indices are int64, 0 if int32

// ---------------- helpers ---------------------------------------------------
__device__ __forceinline__ int ld_idx(const void* ei, long long pos, int is64) {
    if (is64) return (int)(((const long long*)ei)[pos]);
    return ((const int*)ei)[pos];
}

__device__ __forceinline__ void red_add_v4(float* p, float4 v) {
    asm volatile("red.global.add.v4.f32 [%0], {%1,%2,%3,%4};"
                 :: "l"(p), "f"(v.x), "f"(v.y), "f"(v.z), "f"(v.w) : "memory");
}

// ---------------- zeroing ----------------------------------------------------
__global__ void zero_state_kernel() {
    long long i  = (long long)blockIdx.x * blockDim.x + threadIdx.x;
    long long st = (long long)gridDim.x * blockDim.x;
    const long long n_smid = (long long)NM * C;
    for (long long k = i; k < n_smid; k += st) g_smid[k] = 0.0f;
    for (long long k = i; k < NM; k += st)     g_deg[k]  = 0.0f;
    if (i == 0) g_sum[0] = 0.0f;
}

__global__ void zero_out_kernel(float* out, long long n) {
    long long i  = (long long)blockIdx.x * blockDim.x + threadIdx.x;
    long long st = (long long)gridDim.x * blockDim.x;
    for (; i < n; i += st) out[i] = 0.0f;
}

// ---------------- index-width detection -------------------------------------
// If the buffer holds int64 little-endian values < 2^31, every odd 32-bit word
// is zero. 64 consecutive zero odd-words is impossible for real int32 indices.
__global__ void detect_kernel(const void* ei) {
    if (blockIdx.x == 0 && threadIdx.x == 0) {
        const unsigned* w = (const unsigned*)ei;
        int all0 = 1;
        for (int k = 0; k < 64; k++) {
            if (w[2 * k + 1] != 0u) { all0 = 0; break; }
        }
        g_idx64 = all0;
    }
}

// ---------------- stage-1 scatter: g_smid += x_src rows, g_deg += 1 ---------
__global__ void __launch_bounds__(256) scatter1_kernel(const void* ei1, const float* x_src) {
    const int is64 = g_idx64;
    const int lane = threadIdx.x & 31;
    int warp  = (blockIdx.x * blockDim.x + threadIdx.x) >> 5;
    int nwarp = (gridDim.x * blockDim.x) >> 5;
    const float4* xs4 = (const float4*)x_src;
    for (int e = warp; e < NE1; e += nwarp) {
        int src = ld_idx(ei1, e, is64);
        int mid = ld_idx(ei1, (long long)NE1 + e, is64);
        float4 v = xs4[(long long)src * 32 + lane];
        red_add_v4(g_smid + (long long)mid * C + lane * 4, v);
        if (lane == 0) atomicAdd(&g_deg[mid], 1.0f);
    }
}

// ---------------- h GEMM: h = deg*(x_mid@W1^T + b1 + b2) + smid@W2^T --------
// 512 threads: j = t&127 output column, p = t>>7 in {0..3} K-slice of concat K=256
__global__ void __launch_bounds__(512) gemmh_kernel(const float* x_mid,
                                                    const float* W1, const float* b1,
                                                    const float* W2, const float* b2) {
    __shared__ float Ash[8][256];        // [r][0:128]=x_mid row, [128:256]=smid row
    __shared__ float Psh[3][8][128];
    __shared__ float degs[8];
    const int t = threadIdx.x;
    const int j = t & 127;
    const int p = t >> 7;                // 0,1 -> W1 halves ; 2,3 -> W2 halves

    float w[64];
    {
        const float* Wsrc = (p < 2) ? (W1 + j * C + p * 64) : (W2 + j * C + (p - 2) * 64);
        const float4* Wr = (const float4*)Wsrc;
        #pragma unroll
        for (int ii = 0; ii < 16; ii++) {
            float4 x = Wr[ii];
            w[4*ii] = x.x; w[4*ii+1] = x.y; w[4*ii+2] = x.z; w[4*ii+3] = x.w;
        }
    }
    const float bj = b1[j] + b2[j];

    const int r_ld  = t >> 6;            // 0..7
    const int cc_ld = (t & 63) * 4;      // 0..252

    for (int c = blockIdx.x; c < NM / 8; c += gridDim.x) {
        const int m0 = c * 8;
        float4 xv;
        if (cc_ld < 128) xv = *(const float4*)(x_mid + (long long)(m0 + r_ld) * C + cc_ld);
        else             xv = *(const float4*)(g_smid + (long long)(m0 + r_ld) * C + (cc_ld - 128));
        *(float4*)&Ash[r_ld][cc_ld] = xv;
        if (t < 8) degs[t] = g_deg[m0 + t];
        __syncthreads();

        float acc[8];
        #pragma unroll
        for (int r = 0; r < 8; r++) acc[r] = 0.0f;
        const float* Ab = &Ash[0][0] + p * 64;
        #pragma unroll
        for (int i4 = 0; i4 < 16; i4++) {
            #pragma unroll
            for (int r = 0; r < 8; r++) {
                float4 a = *(const float4*)(Ab + r * 256 + i4 * 4);
                acc[r] += w[4*i4] * a.x + w[4*i4+1] * a.y + w[4*i4+2] * a.z + w[4*i4+3] * a.w;
            }
        }
        if (p > 0) {
            #pragma unroll
            for (int r = 0; r < 8; r++) Psh[p - 1][r][j] = acc[r];
        }
        __syncthreads();
        if (p == 0) {
            #pragma unroll
            for (int r = 0; r < 8; r++) {
                float hx = acc[r] + Psh[0][r][j];
                float hs = Psh[1][r][j] + Psh[2][r][j];
                g_h[(long long)(m0 + r) * C + j] = degs[r] * (hx + bj) + hs;
            }
        }
        __syncthreads();
    }
}

// ---------------- generic GEMM: out[M,128] = A[M,128] @ W^T + b -------------
__global__ void __launch_bounds__(256) gemm128_kernel(const float* A, const float* W,
                                                      const float* bias, float* out, int M) {
    __shared__ float Ash[8][128];
    __shared__ float Psh[8][128];
    const int t = threadIdx.x;
    const int j = t & 127;
    const int p = t >> 7;                // 0 or 1: K halves

    float w[64];
    {
        const float4* Wr = (const float4*)(W + j * C + p * 64);
        #pragma unroll
        for (int ii = 0; ii < 16; ii++) {
            float4 x = Wr[ii];
            w[4*ii] = x.x; w[4*ii+1] = x.y; w[4*ii+2] = x.z; w[4*ii+3] = x.w;
        }
    }
    const float bj = bias[j];
    const int nchunk = M >> 3;

    for (int c = blockIdx.x; c < nchunk; c += gridDim.x) {
        const int m0 = c * 8;
        ((float4*)&Ash[0][0])[t] = ((const float4*)(A + (long long)m0 * C))[t];
        __syncthreads();

        float acc[8];
        #pragma unroll
        for (int r = 0; r < 8; r++) acc[r] = 0.0f;
        const float* Ab = &Ash[0][0] + p * 64;
        #pragma unroll
        for (int i4 = 0; i4 < 16; i4++) {
            #pragma unroll
            for (int r = 0; r < 8; r++) {
                float4 a = *(const float4*)(Ab + r * 128 + i4 * 4);
                acc[r] += w[4*i4] * a.x + w[4*i4+1] * a.y + w[4*i4+2] * a.z + w[4*i4+3] * a.w;
            }
        }
        if (p == 1) {
            #pragma unroll
            for (int r = 0; r < 8; r++) Psh[r][j] = acc[r];
        }
        __syncthreads();
        if (p == 0) {
            #pragma unroll
            for (int r = 0; r < 8; r++)
                out[(long long)(m0 + r) * C + j] = acc[r] + Psh[r][j] + bj;
        }
        __syncthreads();
    }
}

// ---------------- edge scores + exp + global sum ----------------------------
// score = (Q[dst] . K[mid]) / sqrt(C); softmax is GLOBAL over all edges.
// Max-subtraction skipped: |score| bounded well below fp32 exp overflow.
__global__ void __launch_bounds__(256) score_kernel(const void* ei2) {
    const int is64 = g_idx64;
    const int lane = threadIdx.x & 31;
    int warp  = (blockIdx.x * blockDim.x + threadIdx.x) >> 5;
    int nwarp = (gridDim.x * blockDim.x) >> 5;
    const float4* Q4 = (const float4*)g_Q;
    const float4* K4 = (const float4*)g_K;
    float wsum = 0.0f;
    for (int e = warp; e < NE2; e += nwarp) {
        int mid = ld_idx(ei2, e, is64);
        int dst = ld_idx(ei2, (long long)NE2 + e, is64);
        float4 q = Q4[(long long)dst * 32 + lane];
        float4 k = K4[(long long)mid * 32 + lane];
        float ppart = q.x * k.x + q.y * k.y + q.z * k.z + q.w * k.w;
        #pragma unroll
        for (int off = 16; off; off >>= 1)
            ppart += __shfl_xor_sync(0xffffffffu, ppart, off);
        float ev = expf(ppart * INV_SQRT_C);
        if (lane == 0) { g_esc[e] = ev; wsum += ev; }
    }
    if (lane == 0) atomicAdd(&g_sum[0], wsum);
}

__global__ void finish_kernel() {
    if (blockIdx.x == 0 && threadIdx.x == 0) g_inv[0] = 1.0f / g_sum[0];
}

// ---------------- final scatter: out[dst] += alpha * V[mid] -----------------
__global__ void __launch_bounds__(256) scatter2_kernel(const void* ei2, float* out) {
    const int is64 = g_idx64;
    const float inv = g_inv[0];
    const int lane = threadIdx.x & 31;
    int warp  = (blockIdx.x * blockDim.x + threadIdx.x) >> 5;
    int nwarp = (gridDim.x * blockDim.x) >> 5;
    const float4* V4 = (const float4*)g_V;
    for (int e = warp; e < NE2; e += nwarp) {
        int mid = ld_idx(ei2, e, is64);
        int dst = ld_idx(ei2, (long long)NE2 + e, is64);
        float alpha = g_esc[e] * inv;
        float4 v = V4[(long long)mid * 32 + lane];
        v.x *= alpha; v.y *= alpha; v.z *= alpha; v.w *= alpha;
        red_add_v4(out + (long long)dst * C + lane * 4, v);
    }
}

// ---------------------------------------------------------------------------
extern "C" void kernel_launch(void* const* d_in, const int* in_sizes, int n_in,
                              void* d_out, int out_size) {
    const float* x_src = (const float*)d_in[0];
    const float* x_mid = (const float*)d_in[1];
    const float* x_dst = (const float*)d_in[2];
    const void*  ei1   = d_in[3];
    const void*  ei2   = d_in[4];
    const float* W1w   = (const float*)d_in[5];
    const float* W1b   = (const float*)d_in[6];
    const float* W2w   = (const float*)d_in[7];
    const float* W2b   = (const float*)d_in[8];
    const float* qw    = (const float*)d_in[9];
    const float* qb    = (const float*)d_in[10];
    const float* kw    = (const float*)d_in[11];
    const float* kb    = (const float*)d_in[12];
    const float* vw    = (const float*)d_in[13];
    const float* vb    = (const float*)d_in[14];
    float* out = (float*)d_out;

    float *p_h, *p_K, *p_V, *p_Q;
    cudaGetSymbolAddress((void**)&p_h, g_h);
    cudaGetSymbolAddress((void**)&p_K, g_K);
    cudaGetSymbolAddress((void**)&p_V, g_V);
    cudaGetSymbolAddress((void**)&p_Q, g_Q);

    zero_state_kernel<<<1024, 256>>>();
    zero_out_kernel<<<1024, 256>>>(out, (long long)ND * C);
    detect_kernel<<<1, 1>>>(ei1);

    // stage 1: scatter raw features + degrees, then dense h GEMM
    scatter1_kernel<<<1184, 256>>>(ei1, x_src);
    gemmh_kernel<<<148, 512>>>(x_mid, W1w, W1b, W2w, W2b);

    // stage 2: node-level K, V, Q GEMMs
    gemm128_kernel<<<296, 256>>>(p_h, kw, kb, p_K, NM);
    gemm128_kernel<<<296, 256>>>(p_h, vw, vb, p_V, NM);
    gemm128_kernel<<<296, 256>>>(x_dst, qw, qb, p_Q, ND);

    // edge scores -> global softmax -> weighted scatter
    score_kernel<<<1184, 256>>>(ei2);
    finish_kernel<<<1, 1>>>();
    scatter2_kernel<<<1184, 256>>>(ei2, out);
}

// round 3
// speedup vs baseline: 1.5166x; 1.5166x over previous
#include <cuda_runtime.h>
#include <cuda_bf16.h>
#include <cstdint>
#include <math.h>

// ---------------------------------------------------------------------------
// AtomicRouteConv — restructured GNN pipeline.
// GEMMs on HMMA (mma.sync m16n8k16 bf16) with split-bf16 fp32 emulation:
//   A = Ah + Al, B = Bh + Bl;  D = Ah*Bh + Ah*Bl + Al*Bh  (err ~1.5e-5)
// (tcgen05 unavailable: harness compiles for sm_103 base target, not sm_103a)
// ---------------------------------------------------------------------------

#define C      128
#define NM     50000
#define ND     50000
#define NE1    640000
#define NE2    640000
#define INV_SQRT_C 0.08838834764831843f

// padded smem row: 128 bf16 = 64 words, pad to 68 words (conflict-free frags)
#define RP 68
#define RP8 (8*RP)
#define AREA (128*RP)            // words per hi or lo region (34816 B)

// ---------------- scratch ----------------------------------------------------
__device__ __align__(16) float g_smid[NM * C];
__device__ __align__(16) float g_deg [NM];
__device__ __align__(16) float g_h   [NM * C];
__device__ __align__(16) float g_K   [NM * C];
__device__ __align__(16) float g_V   [NM * C];
__device__ __align__(16) float g_Q   [ND * C];
__device__ __align__(16) float g_esc [NE2];
__device__ float g_sum[1];
__device__ float g_inv[1];
__device__ int   g_idx64;

// ---------------- helpers ---------------------------------------------------
__device__ __forceinline__ int ld_idx(const void* ei, long long pos, int is64) {
    if (is64) return (int)(((const long long*)ei)[pos]);
    return ((const int*)ei)[pos];
}
__device__ __forceinline__ void red_add_v4(float* p, float4 v) {
    asm volatile("red.global.add.v4.f32 [%0], {%1,%2,%3,%4};"
                 :: "l"(p), "f"(v.x), "f"(v.y), "f"(v.z), "f"(v.w) : "memory");
}
// split two fp32 into packed bf16x2 hi + lo (lo-half = f0, hi-half = f1)
__device__ __forceinline__ void split2(float f0, float f1, uint32_t& h, uint32_t& l) {
    uint32_t hp;
    asm("cvt.rn.bf16x2.f32 %0, %1, %2;" : "=r"(hp) : "f"(f1), "f"(f0));
    float f0h = __uint_as_float(hp << 16);
    float f1h = __uint_as_float(hp & 0xffff0000u);
    float r0 = f0 - f0h, r1 = f1 - f1h;
    asm("cvt.rn.bf16x2.f32 %0, %1, %2;" : "=r"(l) : "f"(r1), "f"(r0));
    h = hp;
}
__device__ __forceinline__ void mma_bf16(float* c, const uint32_t* a,
                                         uint32_t b0, uint32_t b1) {
    asm volatile("mma.sync.aligned.m16n8k16.row.col.f32.bf16.bf16.f32 "
        "{%0,%1,%2,%3}, {%4,%5,%6,%7}, {%8,%9}, {%0,%1,%2,%3};"
        : "+f"(c[0]), "+f"(c[1]), "+f"(c[2]), "+f"(c[3])
        : "r"(a[0]), "r"(a[1]), "r"(a[2]), "r"(a[3]), "r"(b0), "r"(b1));
}

// convert a 128x128 fp32 matrix (guarded rows) into hi/lo bf16 smem regions,
// optional per-row scale. 256 threads: thread t -> row t>>1, col half (t&1)*64.
__device__ __forceinline__ void convert_tile(const float* __restrict__ A, int m0, int M,
                                             uint32_t* __restrict__ Dh,
                                             uint32_t* __restrict__ Dl,
                                             const float* __restrict__ rowscale) {
    const int t = threadIdx.x;
    const int r = t >> 1, c0 = (t & 1) * 64;
    const int row = m0 + r;
    const bool v = row < M;
    const float s = (rowscale && v) ? rowscale[row] : 1.0f;
    const float4* Ar = (const float4*)(A + (size_t)row * C + c0);
    const int wb = r * RP + (c0 >> 1);
    #pragma unroll
    for (int i = 0; i < 16; i++) {
        float4 x = v ? Ar[i] : make_float4(0.f, 0.f, 0.f, 0.f);
        uint32_t h0, l0, h1, l1;
        split2(s * x.x, s * x.y, h0, l0);
        split2(s * x.z, s * x.w, h1, l1);
        Dh[wb + i*2]   = h0; Dh[wb + i*2+1] = h1;
        Dl[wb + i*2]   = l0; Dl[wb + i*2+1] = l1;
    }
}

// warp-tile compute: acc[16][4] += A(128x128) @ W^T with split-bf16 3-pass.
__device__ __forceinline__ void tile_compute(const uint32_t* __restrict__ Ah,
                                             const uint32_t* __restrict__ Al,
                                             const uint32_t* __restrict__ Wh,
                                             const uint32_t* __restrict__ Wl,
                                             float* __restrict__ acc,
                                             int w, int g, int tig) {
    #pragma unroll 1
    for (int ks = 0; ks < 8; ks++) {
        uint32_t ah[4], al[4];
        const int ab = (w * 16 + g) * RP + ks * 8 + tig;
        ah[0] = Ah[ab];     ah[1] = Ah[ab + RP8];
        ah[2] = Ah[ab + 4]; ah[3] = Ah[ab + RP8 + 4];
        al[0] = Al[ab];     al[1] = Al[ab + RP8];
        al[2] = Al[ab + 4]; al[3] = Al[ab + RP8 + 4];
        #pragma unroll
        for (int nt = 0; nt < 16; nt++) {
            const int nb = (nt * 8 + g) * RP + ks * 8 + tig;
            uint32_t bh0 = Wh[nb], bh1 = Wh[nb + 4];
            uint32_t bl0 = Wl[nb], bl1 = Wl[nb + 4];
            float* cc = acc + nt * 4;
            mma_bf16(cc, ah, bh0, bh1);
            mma_bf16(cc, ah, bl0, bl1);
            mma_bf16(cc, al, bh0, bh1);
        }
    }
}

// convert a weight matrix [128][128] into hi/lo smem regions
__device__ __forceinline__ void convert_w(const float* __restrict__ W,
                                          uint32_t* __restrict__ Wh,
                                          uint32_t* __restrict__ Wl) {
    const int t = threadIdx.x;
    const int r = t >> 1, c0 = (t & 1) * 64;
    const float4* Wr = (const float4*)(W + r * C + c0);
    const int wb = r * RP + (c0 >> 1);
    #pragma unroll
    for (int i = 0; i < 16; i++) {
        float4 x = Wr[i];
        uint32_t h0, l0, h1, l1;
        split2(x.x, x.y, h0, l0);
        split2(x.z, x.w, h1, l1);
        Wh[wb + i*2]   = h0; Wh[wb + i*2+1] = h1;
        Wl[wb + i*2]   = l0; Wl[wb + i*2+1] = l1;
    }
}

#define SMG_BYTES (4 * AREA * 4 + 512)
#define SMH_BYTES (6 * AREA * 4 + 512)

// ---------------- generic GEMM: out[M,128] = A[M,128] @ W^T + b -------------
__global__ void __launch_bounds__(256) gemm_mma_kernel(
    const float* __restrict__ A, const float* __restrict__ W,
    const float* __restrict__ bias, float* __restrict__ out, int M)
{
    extern __shared__ uint32_t sm[];
    uint32_t* Ah = sm;
    uint32_t* Al = sm + AREA;
    uint32_t* Wh = sm + 2 * AREA;
    uint32_t* Wl = sm + 3 * AREA;
    float* bsh = (float*)(sm + 4 * AREA);

    const int t = threadIdx.x;
    convert_w(W, Wh, Wl);
    if (t < 128) bsh[t] = bias[t];

    const int w = t >> 5, lane = t & 31, g = lane >> 2, tig = lane & 3;
    const int ntiles = (M + 127) >> 7;

    for (int tile = blockIdx.x; tile < ntiles; tile += gridDim.x) {
        const int m0 = tile << 7;
        __syncthreads();
        convert_tile(A, m0, M, Ah, Al, (const float*)0);
        __syncthreads();

        float acc[64];
        #pragma unroll
        for (int i = 0; i < 64; i++) acc[i] = 0.0f;
        tile_compute(Ah, Al, Wh, Wl, acc, w, g, tig);

        const int r0 = m0 + w * 16 + g;
        const int r1 = r0 + 8;
        #pragma unroll
        for (int nt = 0; nt < 16; nt++) {
            const int c = nt * 8 + tig * 2;
            const float b0 = bsh[c], b1 = bsh[c + 1];
            if (r0 < M) {
                float2 o = { acc[nt*4+0] + b0, acc[nt*4+1] + b1 };
                *(float2*)(out + (size_t)r0 * C + c) = o;
            }
            if (r1 < M) {
                float2 o = { acc[nt*4+2] + b0, acc[nt*4+3] + b1 };
                *(float2*)(out + (size_t)r1 * C + c) = o;
            }
        }
    }
}

// ---------------- h GEMM: h = deg*(x_mid@W1^T) + smid@W2^T + deg*(b1+b2) ----
// (deg folded into A rows before the MMA so one accumulator suffices)
__global__ void __launch_bounds__(256) gemmh_mma_kernel(
    const float* __restrict__ x_mid,
    const float* __restrict__ W1, const float* __restrict__ b1,
    const float* __restrict__ W2, const float* __restrict__ b2)
{
    extern __shared__ uint32_t sm[];
    uint32_t* Ah  = sm;
    uint32_t* Al  = sm + AREA;
    uint32_t* W1h = sm + 2 * AREA;
    uint32_t* W1l = sm + 3 * AREA;
    uint32_t* W2h = sm + 4 * AREA;
    uint32_t* W2l = sm + 5 * AREA;
    float* bsh = (float*)(sm + 6 * AREA);

    const int t = threadIdx.x;
    convert_w(W1, W1h, W1l);
    convert_w(W2, W2h, W2l);
    if (t < 128) bsh[t] = b1[t] + b2[t];

    const int w = t >> 5, lane = t & 31, g = lane >> 2, tig = lane & 3;
    const int ntiles = (NM + 127) >> 7;

    for (int tile = blockIdx.x; tile < ntiles; tile += gridDim.x) {
        const int m0 = tile << 7;
        float acc[64];
        #pragma unroll
        for (int i = 0; i < 64; i++) acc[i] = 0.0f;

        __syncthreads();
        convert_tile(x_mid, m0, NM, Ah, Al, g_deg);   // rows scaled by deg
        __syncthreads();
        tile_compute(Ah, Al, W1h, W1l, acc, w, g, tig);

        __syncthreads();
        convert_tile(g_smid, m0, NM, Ah, Al, (const float*)0);
        __syncthreads();
        tile_compute(Ah, Al, W2h, W2l, acc, w, g, tig);

        const int r0 = m0 + w * 16 + g;
        const int r1 = r0 + 8;
        const float d0 = (r0 < NM) ? g_deg[r0] : 0.0f;
        const float d1 = (r1 < NM) ? g_deg[r1] : 0.0f;
        #pragma unroll
        for (int nt = 0; nt < 16; nt++) {
            const int c = nt * 8 + tig * 2;
            const float b0 = bsh[c], b1v = bsh[c + 1];
            if (r0 < NM) {
                float2 o = { acc[nt*4+0] + d0 * b0, acc[nt*4+1] + d0 * b1v };
                *(float2*)(g_h + (size_t)r0 * C + c) = o;
            }
            if (r1 < NM) {
                float2 o = { acc[nt*4+2] + d1 * b0, acc[nt*4+3] + d1 * b1v };
                *(float2*)(g_h + (size_t)r1 * C + c) = o;
            }
        }
    }
}

// ---------------- zeroing ----------------------------------------------------
__global__ void zero_state_kernel() {
    long long i  = (long long)blockIdx.x * blockDim.x + threadIdx.x;
    long long st = (long long)gridDim.x * blockDim.x;
    const long long n_smid = (long long)NM * C;
    for (long long k = i; k < n_smid; k += st) g_smid[k] = 0.0f;
    for (long long k = i; k < NM; k += st)     g_deg[k]  = 0.0f;
    if (i == 0) g_sum[0] = 0.0f;
}
__global__ void zero_out_kernel(float* out, long long n) {
    long long i  = (long long)blockIdx.x * blockDim.x + threadIdx.x;
    long long st = (long long)gridDim.x * blockDim.x;
    for (; i < n; i += st) out[i] = 0.0f;
}
__global__ void detect_kernel(const void* ei) {
    if (blockIdx.x == 0 && threadIdx.x == 0) {
        const unsigned* w = (const unsigned*)ei;
        int all0 = 1;
        for (int k = 0; k < 64; k++)
            if (w[2 * k + 1] != 0u) { all0 = 0; break; }
        g_idx64 = all0;
    }
}

// ---------------- stage-1 scatter -------------------------------------------
__global__ void __launch_bounds__(256) scatter1_kernel(const void* ei1, const float* x_src) {
    const int is64 = g_idx64;
    const int lane = threadIdx.x & 31;
    int warp  = (blockIdx.x * blockDim.x + threadIdx.x) >> 5;
    int nwarp = (gridDim.x * blockDim.x) >> 5;
    const float4* xs4 = (const float4*)x_src;
    for (int e = warp; e < NE1; e += nwarp) {
        int src = ld_idx(ei1, e, is64);
        int mid = ld_idx(ei1, (long long)NE1 + e, is64);
        float4 v = xs4[(long long)src * 32 + lane];
        red_add_v4(g_smid + (long long)mid * C + lane * 4, v);
        if (lane == 0) atomicAdd(&g_deg[mid], 1.0f);
    }
}

// ---------------- edge scores + exp + global sum ----------------------------
__global__ void __launch_bounds__(256) score_kernel(const void* ei2) {
    const int is64 = g_idx64;
    const int lane = threadIdx.x & 31;
    int warp  = (blockIdx.x * blockDim.x + threadIdx.x) >> 5;
    int nwarp = (gridDim.x * blockDim.x) >> 5;
    const float4* Q4 = (const float4*)g_Q;
    const float4* K4 = (const float4*)g_K;
    float wsum = 0.0f;
    for (int e = warp; e < NE2; e += nwarp) {
        int mid = ld_idx(ei2, e, is64);
        int dst = ld_idx(ei2, (long long)NE2 + e, is64);
        float4 q = Q4[(long long)dst * 32 + lane];
        float4 k = K4[(long long)mid * 32 + lane];
        float ppart = q.x * k.x + q.y * k.y + q.z * k.z + q.w * k.w;
        #pragma unroll
        for (int off = 16; off; off >>= 1)
            ppart += __shfl_xor_sync(0xffffffffu, ppart, off);
        float ev = expf(ppart * INV_SQRT_C);
        if (lane == 0) { g_esc[e] = ev; wsum += ev; }
    }
    if (lane == 0) atomicAdd(&g_sum[0], wsum);
}

__global__ void finish_kernel() {
    if (blockIdx.x == 0 && threadIdx.x == 0) g_inv[0] = 1.0f / g_sum[0];
}

// ---------------- final scatter ----------------------------------------------
__global__ void __launch_bounds__(256) scatter2_kernel(const void* ei2, float* out) {
    const int is64 = g_idx64;
    const float inv = g_inv[0];
    const int lane = threadIdx.x & 31;
    int warp  = (blockIdx.x * blockDim.x + threadIdx.x) >> 5;
    int nwarp = (gridDim.x * blockDim.x) >> 5;
    const float4* V4 = (const float4*)g_V;
    for (int e = warp; e < NE2; e += nwarp) {
        int mid = ld_idx(ei2, e, is64);
        int dst = ld_idx(ei2, (long long)NE2 + e, is64);
        float alpha = g_esc[e] * inv;
        float4 v = V4[(long long)mid * 32 + lane];
        v.x *= alpha; v.y *= alpha; v.z *= alpha; v.w *= alpha;
        red_add_v4(out + (long long)dst * C + lane * 4, v);
    }
}

// ---------------------------------------------------------------------------
extern "C" void kernel_launch(void* const* d_in, const int* in_sizes, int n_in,
                              void* d_out, int out_size) {
    const float* x_src = (const float*)d_in[0];
    const float* x_mid = (const float*)d_in[1];
    const float* x_dst = (const float*)d_in[2];
    const void*  ei1   = d_in[3];
    const void*  ei2   = d_in[4];
    const float* W1w   = (const float*)d_in[5];
    const float* W1b   = (const float*)d_in[6];
    const float* W2w   = (const float*)d_in[7];
    const float* W2b   = (const float*)d_in[8];
    const float* qw    = (const float*)d_in[9];
    const float* qb    = (const float*)d_in[10];
    const float* kw    = (const float*)d_in[11];
    const float* kb    = (const float*)d_in[12];
    const float* vw    = (const float*)d_in[13];
    const float* vb    = (const float*)d_in[14];
    float* out = (float*)d_out;

    float *p_h, *p_K, *p_V, *p_Q;
    cudaGetSymbolAddress((void**)&p_h, g_h);
    cudaGetSymbolAddress((void**)&p_K, g_K);
    cudaGetSymbolAddress((void**)&p_V, g_V);
    cudaGetSymbolAddress((void**)&p_Q, g_Q);

    static int attr_done = 0;
    if (!attr_done) {
        cudaFuncSetAttribute(gemm_mma_kernel,
                             cudaFuncAttributeMaxDynamicSharedMemorySize, SMG_BYTES);
        cudaFuncSetAttribute(gemmh_mma_kernel,
                             cudaFuncAttributeMaxDynamicSharedMemorySize, SMH_BYTES);
        attr_done = 1;
    }

    zero_state_kernel<<<1024, 256>>>();
    zero_out_kernel<<<1024, 256>>>(out, (long long)ND * C);
    detect_kernel<<<1, 1>>>(ei1);

    // stage 1: scatter raw features + degrees, then dense h GEMM (HMMA)
    scatter1_kernel<<<1184, 256>>>(ei1, x_src);
    gemmh_mma_kernel<<<148, 256, SMH_BYTES>>>(x_mid, W1w, W1b, W2w, W2b);

    // stage 2: node-level K, V, Q GEMMs (HMMA)
    gemm_mma_kernel<<<148, 256, SMG_BYTES>>>(p_h, kw, kb, p_K, NM);
    gemm_mma_kernel<<<148, 256, SMG_BYTES>>>(p_h, vw, vb, p_V, NM);
    gemm_mma_kernel<<<148, 256, SMG_BYTES>>>(x_dst, qw, qb, p_Q, ND);

    // edge scores -> global softmax -> weighted scatter
    score_kernel<<<1184, 256>>>(ei2);
    finish_kernel<<<1, 1>>>();
    scatter2_kernel<<<1184, 256>>>(ei2, out);
}

// round 5
// speedup vs baseline: 1.5658x; 1.0324x over previous
#include <cuda_runtime.h>
#include <cuda_bf16.h>
#include <cstdint>
#include <math.h>

// ---------------------------------------------------------------------------
// AtomicRouteConv — restructured GNN pipeline.
// GEMMs on HMMA (mma.sync m16n8k16 bf16) with split-bf16 fp32 emulation:
//   A = Ah + Al, B = Bh + Bl;  D = Ah*Bh + Ah*Bl + Al*Bh  (err ~1.5e-5)
// R5 (= R4 resubmit after infra failure): fused K+V GEMM, x4-unrolled edge
// scatters, vectorized zeroing, no static guards.
// ---------------------------------------------------------------------------

#define C      128
#define NM     50000
#define ND     50000
#define NE1    640000
#define NE2    640000
#define INV_SQRT_C 0.08838834764831843f

// padded smem row: 128 bf16 = 64 words, pad to 68 words (conflict-free frags)
#define RP 68
#define RP8 (8*RP)
#define AREA (128*RP)            // words per hi or lo region (34816 B)

// ---------------- scratch ----------------------------------------------------
__device__ __align__(16) float g_smid[NM * C];
__device__ __align__(16) float g_deg [NM + 48];   // padded for float4 zeroing
__device__ __align__(16) float g_h   [NM * C];
__device__ __align__(16) float g_K   [NM * C];
__device__ __align__(16) float g_V   [NM * C];
__device__ __align__(16) float g_Q   [ND * C];
__device__ __align__(16) float g_esc [NE2];
__device__ float g_sum[1];
__device__ int   g_idx64;

// ---------------- helpers ---------------------------------------------------
__device__ __forceinline__ int ld_idx(const void* ei, long long pos, int is64) {
    if (is64) return (int)(((const long long*)ei)[pos]);
    return ((const int*)ei)[pos];
}
__device__ __forceinline__ void red_add_v4(float* p, float4 v) {
    asm volatile("red.global.add.v4.f32 [%0], {%1,%2,%3,%4};"
                 :: "l"(p), "f"(v.x), "f"(v.y), "f"(v.z), "f"(v.w) : "memory");
}
// split two fp32 into packed bf16x2 hi + lo (lo-half = f0, hi-half = f1)
__device__ __forceinline__ void split2(float f0, float f1, uint32_t& h, uint32_t& l) {
    uint32_t hp;
    asm("cvt.rn.bf16x2.f32 %0, %1, %2;" : "=r"(hp) : "f"(f1), "f"(f0));
    float f0h = __uint_as_float(hp << 16);
    float f1h = __uint_as_float(hp & 0xffff0000u);
    float r0 = f0 - f0h, r1 = f1 - f1h;
    asm("cvt.rn.bf16x2.f32 %0, %1, %2;" : "=r"(l) : "f"(r1), "f"(r0));
    h = hp;
}
__device__ __forceinline__ void mma_bf16(float* c, const uint32_t* a,
                                         uint32_t b0, uint32_t b1) {
    asm volatile("mma.sync.aligned.m16n8k16.row.col.f32.bf16.bf16.f32 "
        "{%0,%1,%2,%3}, {%4,%5,%6,%7}, {%8,%9}, {%0,%1,%2,%3};"
        : "+f"(c[0]), "+f"(c[1]), "+f"(c[2]), "+f"(c[3])
        : "r"(a[0]), "r"(a[1]), "r"(a[2]), "r"(a[3]), "r"(b0), "r"(b1));
}

// convert a 128x128 fp32 tile (guarded rows) into hi/lo bf16 smem regions,
// optional per-row scale. 256 threads: thread t -> row t>>1, col half (t&1)*64.
__device__ __forceinline__ void convert_tile(const float* __restrict__ A, int m0, int M,
                                             uint32_t* __restrict__ Dh,
                                             uint32_t* __restrict__ Dl,
                                             const float* __restrict__ rowscale) {
    const int t = threadIdx.x;
    const int r = t >> 1, c0 = (t & 1) * 64;
    const int row = m0 + r;
    const bool v = row < M;
    const float s = (rowscale && v) ? rowscale[row] : 1.0f;
    const float4* Ar = (const float4*)(A + (size_t)row * C + c0);
    const int wb = r * RP + (c0 >> 1);
    #pragma unroll
    for (int i = 0; i < 16; i++) {
        float4 x = v ? Ar[i] : make_float4(0.f, 0.f, 0.f, 0.f);
        uint32_t h0, l0, h1, l1;
        split2(s * x.x, s * x.y, h0, l0);
        split2(s * x.z, s * x.w, h1, l1);
        Dh[wb + i*2]   = h0; Dh[wb + i*2+1] = h1;
        Dl[wb + i*2]   = l0; Dl[wb + i*2+1] = l1;
    }
}

// warp-tile compute: acc[16][4] += A(128x128) @ W^T with split-bf16 3-pass.
__device__ __forceinline__ void tile_compute(const uint32_t* __restrict__ Ah,
                                             const uint32_t* __restrict__ Al,
                                             const uint32_t* __restrict__ Wh,
                                             const uint32_t* __restrict__ Wl,
                                             float* __restrict__ acc,
                                             int w, int g, int tig) {
    #pragma unroll 1
    for (int ks = 0; ks < 8; ks++) {
        uint32_t ah[4], al[4];
        const int ab = (w * 16 + g) * RP + ks * 8 + tig;
        ah[0] = Ah[ab];     ah[1] = Ah[ab + RP8];
        ah[2] = Ah[ab + 4]; ah[3] = Ah[ab + RP8 + 4];
        al[0] = Al[ab];     al[1] = Al[ab + RP8];
        al[2] = Al[ab + 4]; al[3] = Al[ab + RP8 + 4];
        #pragma unroll
        for (int nt = 0; nt < 16; nt++) {
            const int nb = (nt * 8 + g) * RP + ks * 8 + tig;
            uint32_t bh0 = Wh[nb], bh1 = Wh[nb + 4];
            uint32_t bl0 = Wl[nb], bl1 = Wl[nb + 4];
            float* cc = acc + nt * 4;
            mma_bf16(cc, ah, bh0, bh1);
            mma_bf16(cc, ah, bl0, bl1);
            mma_bf16(cc, al, bh0, bh1);
        }
    }
}

// convert a weight matrix [128][128] into hi/lo smem regions
__device__ __forceinline__ void convert_w(const float* __restrict__ W,
                                          uint32_t* __restrict__ Wh,
                                          uint32_t* __restrict__ Wl) {
    const int t = threadIdx.x;
    const int r = t >> 1, c0 = (t & 1) * 64;
    const float4* Wr = (const float4*)(W + r * C + c0);
    const int wb = r * RP + (c0 >> 1);
    #pragma unroll
    for (int i = 0; i < 16; i++) {
        float4 x = Wr[i];
        uint32_t h0, l0, h1, l1;
        split2(x.x, x.y, h0, l0);
        split2(x.z, x.w, h1, l1);
        Wh[wb + i*2]   = h0; Wh[wb + i*2+1] = h1;
        Wl[wb + i*2]   = l0; Wl[wb + i*2+1] = l1;
    }
}

__device__ __forceinline__ void epilogue_write(const float* __restrict__ acc,
                                               const float* __restrict__ bsh,
                                               float* __restrict__ out,
                                               int m0, int M, int w, int g, int tig) {
    const int r0 = m0 + w * 16 + g;
    const int r1 = r0 + 8;
    #pragma unroll
    for (int nt = 0; nt < 16; nt++) {
        const int c = nt * 8 + tig * 2;
        const float b0 = bsh[c], b1 = bsh[c + 1];
        if (r0 < M) {
            float2 o = { acc[nt*4+0] + b0, acc[nt*4+1] + b1 };
            *(float2*)(out + (size_t)r0 * C + c) = o;
        }
        if (r1 < M) {
            float2 o = { acc[nt*4+2] + b0, acc[nt*4+3] + b1 };
            *(float2*)(out + (size_t)r1 * C + c) = o;
        }
    }
}

#define SMG_BYTES  (4 * AREA * 4 + 512)
#define SMH_BYTES  (6 * AREA * 4 + 512)
#define SMKV_BYTES (6 * AREA * 4 + 1024)

// ---------------- generic GEMM: out[M,128] = A[M,128] @ W^T + b -------------
__global__ void __launch_bounds__(256) gemm_mma_kernel(
    const float* __restrict__ A, const float* __restrict__ W,
    const float* __restrict__ bias, float* __restrict__ out, int M)
{
    extern __shared__ uint32_t sm[];
    uint32_t* Ah = sm;
    uint32_t* Al = sm + AREA;
    uint32_t* Wh = sm + 2 * AREA;
    uint32_t* Wl = sm + 3 * AREA;
    float* bsh = (float*)(sm + 4 * AREA);

    const int t = threadIdx.x;
    convert_w(W, Wh, Wl);
    if (t < 128) bsh[t] = bias[t];

    const int w = t >> 5, lane = t & 31, g = lane >> 2, tig = lane & 3;
    const int ntiles = (M + 127) >> 7;

    for (int tile = blockIdx.x; tile < ntiles; tile += gridDim.x) {
        const int m0 = tile << 7;
        __syncthreads();
        convert_tile(A, m0, M, Ah, Al, (const float*)0);
        __syncthreads();

        float acc[64];
        #pragma unroll
        for (int i = 0; i < 64; i++) acc[i] = 0.0f;
        tile_compute(Ah, Al, Wh, Wl, acc, w, g, tig);
        epilogue_write(acc, bsh, out, m0, M, w, g, tig);
    }
}

// ---------------- fused K+V GEMM: K/V[M,128] = A @ {Wk,Wv}^T + {bk,bv} ------
__global__ void __launch_bounds__(256) gemm_kv_kernel(
    const float* __restrict__ A,
    const float* __restrict__ Wk, const float* __restrict__ bk, float* __restrict__ outK,
    const float* __restrict__ Wv, const float* __restrict__ bv, float* __restrict__ outV,
    int M)
{
    extern __shared__ uint32_t sm[];
    uint32_t* Ah  = sm;
    uint32_t* Al  = sm + AREA;
    uint32_t* Wkh = sm + 2 * AREA;
    uint32_t* Wkl = sm + 3 * AREA;
    uint32_t* Wvh = sm + 4 * AREA;
    uint32_t* Wvl = sm + 5 * AREA;
    float* bshk = (float*)(sm + 6 * AREA);
    float* bshv = bshk + 128;

    const int t = threadIdx.x;
    convert_w(Wk, Wkh, Wkl);
    convert_w(Wv, Wvh, Wvl);
    if (t < 128) bshk[t] = bk[t];
    else         bshv[t - 128] = bv[t - 128];

    const int w = t >> 5, lane = t & 31, g = lane >> 2, tig = lane & 3;
    const int ntiles = (M + 127) >> 7;

    for (int tile = blockIdx.x; tile < ntiles; tile += gridDim.x) {
        const int m0 = tile << 7;
        __syncthreads();
        convert_tile(A, m0, M, Ah, Al, (const float*)0);
        __syncthreads();

        float acc[64];
        #pragma unroll
        for (int i = 0; i < 64; i++) acc[i] = 0.0f;
        tile_compute(Ah, Al, Wkh, Wkl, acc, w, g, tig);
        epilogue_write(acc, bshk, outK, m0, M, w, g, tig);

        #pragma unroll
        for (int i = 0; i < 64; i++) acc[i] = 0.0f;
        tile_compute(Ah, Al, Wvh, Wvl, acc, w, g, tig);
        epilogue_write(acc, bshv, outV, m0, M, w, g, tig);
    }
}

// ---------------- h GEMM: h = deg*(x_mid@W1^T) + smid@W2^T + deg*(b1+b2) ----
__global__ void __launch_bounds__(256) gemmh_mma_kernel(
    const float* __restrict__ x_mid,
    const float* __restrict__ W1, const float* __restrict__ b1,
    const float* __restrict__ W2, const float* __restrict__ b2)
{
    extern __shared__ uint32_t sm[];
    uint32_t* Ah  = sm;
    uint32_t* Al  = sm + AREA;
    uint32_t* W1h = sm + 2 * AREA;
    uint32_t* W1l = sm + 3 * AREA;
    uint32_t* W2h = sm + 4 * AREA;
    uint32_t* W2l = sm + 5 * AREA;
    float* bsh = (float*)(sm + 6 * AREA);

    const int t = threadIdx.x;
    convert_w(W1, W1h, W1l);
    convert_w(W2, W2h, W2l);
    if (t < 128) bsh[t] = b1[t] + b2[t];

    const int w = t >> 5, lane = t & 31, g = lane >> 2, tig = lane & 3;
    const int ntiles = (NM + 127) >> 7;

    for (int tile = blockIdx.x; tile < ntiles; tile += gridDim.x) {
        const int m0 = tile << 7;
        float acc[64];
        #pragma unroll
        for (int i = 0; i < 64; i++) acc[i] = 0.0f;

        __syncthreads();
        convert_tile(x_mid, m0, NM, Ah, Al, g_deg);   // rows scaled by deg
        __syncthreads();
        tile_compute(Ah, Al, W1h, W1l, acc, w, g, tig);

        __syncthreads();
        convert_tile(g_smid, m0, NM, Ah, Al, (const float*)0);
        __syncthreads();
        tile_compute(Ah, Al, W2h, W2l, acc, w, g, tig);

        const int r0 = m0 + w * 16 + g;
        const int r1 = r0 + 8;
        const float d0 = (r0 < NM) ? g_deg[r0] : 0.0f;
        const float d1 = (r1 < NM) ? g_deg[r1] : 0.0f;
        #pragma unroll
        for (int nt = 0; nt < 16; nt++) {
            const int c = nt * 8 + tig * 2;
            const float b0 = bsh[c], b1v = bsh[c + 1];
            if (r0 < NM) {
                float2 o = { acc[nt*4+0] + d0 * b0, acc[nt*4+1] + d0 * b1v };
                *(float2*)(g_h + (size_t)r0 * C + c) = o;
            }
            if (r1 < NM) {
                float2 o = { acc[nt*4+2] + d1 * b0, acc[nt*4+3] + d1 * b1v };
                *(float2*)(g_h + (size_t)r1 * C + c) = o;
            }
        }
    }
}

// ---------------- zeroing (vectorized, one kernel) ---------------------------
__global__ void __launch_bounds__(256) zero_all_kernel(float4* out4) {
    const long long i  = (long long)blockIdx.x * blockDim.x + threadIdx.x;
    const long long st = (long long)gridDim.x * blockDim.x;
    const float4 z = make_float4(0.f, 0.f, 0.f, 0.f);
    float4* s4 = (float4*)g_smid;
    const long long n4 = (long long)NM * C / 4;
    for (long long k = i; k < n4; k += st) s4[k] = z;
    float4* d4 = (float4*)g_deg;
    for (long long k = i; k < NM / 4; k += st) d4[k] = z;
    const long long o4 = (long long)ND * C / 4;
    for (long long k = i; k < o4; k += st) out4[k] = z;
    if (i == 0) g_sum[0] = 0.0f;
}
__global__ void detect_kernel(const void* ei) {
    if (blockIdx.x == 0 && threadIdx.x == 0) {
        const unsigned* w = (const unsigned*)ei;
        int all0 = 1;
        for (int k = 0; k < 64; k++)
            if (w[2 * k + 1] != 0u) { all0 = 0; break; }
        g_idx64 = all0;
    }
}

// ---------------- stage-1 scatter (x4 unrolled) ------------------------------
__global__ void __launch_bounds__(256) scatter1_kernel(const void* ei1, const float* x_src) {
    const int is64 = g_idx64;
    const int lane = threadIdx.x & 31;
    const int warp  = (blockIdx.x * blockDim.x + threadIdx.x) >> 5;
    const int nwarp = (gridDim.x * blockDim.x) >> 5;
    const float4* xs4 = (const float4*)x_src;
    int e = warp;
    for (; e + 3 * nwarp < NE1; e += 4 * nwarp) {
        int s[4], m[4];
        #pragma unroll
        for (int j = 0; j < 4; j++) {
            s[j] = ld_idx(ei1, e + j * nwarp, is64);
            m[j] = ld_idx(ei1, (long long)NE1 + e + j * nwarp, is64);
        }
        float4 v[4];
        #pragma unroll
        for (int j = 0; j < 4; j++) v[j] = xs4[(size_t)s[j] * 32 + lane];
        #pragma unroll
        for (int j = 0; j < 4; j++)
            red_add_v4(g_smid + (size_t)m[j] * C + lane * 4, v[j]);
        if (lane == 0) {
            #pragma unroll
            for (int j = 0; j < 4; j++) atomicAdd(&g_deg[m[j]], 1.0f);
        }
    }
    for (; e < NE1; e += nwarp) {
        int src = ld_idx(ei1, e, is64);
        int mid = ld_idx(ei1, (long long)NE1 + e, is64);
        float4 v = xs4[(size_t)src * 32 + lane];
        red_add_v4(g_smid + (size_t)mid * C + lane * 4, v);
        if (lane == 0) atomicAdd(&g_deg[mid], 1.0f);
    }
}

// ---------------- edge scores + exp + global sum (x2 unrolled) ---------------
__global__ void __launch_bounds__(256) score_kernel(const void* ei2) {
    const int is64 = g_idx64;
    const int lane = threadIdx.x & 31;
    const int warp  = (blockIdx.x * blockDim.x + threadIdx.x) >> 5;
    const int nwarp = (gridDim.x * blockDim.x) >> 5;
    const float4* Q4 = (const float4*)g_Q;
    const float4* K4 = (const float4*)g_K;
    float wsum = 0.0f;
    int e = warp;
    for (; e + nwarp < NE2; e += 2 * nwarp) {
        int m0 = ld_idx(ei2, e, is64);
        int m1 = ld_idx(ei2, e + nwarp, is64);
        int d0 = ld_idx(ei2, (long long)NE2 + e, is64);
        int d1 = ld_idx(ei2, (long long)NE2 + e + nwarp, is64);
        float4 q0 = Q4[(size_t)d0 * 32 + lane];
        float4 k0 = K4[(size_t)m0 * 32 + lane];
        float4 q1 = Q4[(size_t)d1 * 32 + lane];
        float4 k1 = K4[(size_t)m1 * 32 + lane];
        float p0 = q0.x*k0.x + q0.y*k0.y + q0.z*k0.z + q0.w*k0.w;
        float p1 = q1.x*k1.x + q1.y*k1.y + q1.z*k1.z + q1.w*k1.w;
        #pragma unroll
        for (int off = 16; off; off >>= 1) {
            p0 += __shfl_xor_sync(0xffffffffu, p0, off);
            p1 += __shfl_xor_sync(0xffffffffu, p1, off);
        }
        float e0 = expf(p0 * INV_SQRT_C);
        float e1 = expf(p1 * INV_SQRT_C);
        if (lane == 0) { g_esc[e] = e0; g_esc[e + nwarp] = e1; wsum += e0 + e1; }
    }
    for (; e < NE2; e += nwarp) {
        int mid = ld_idx(ei2, e, is64);
        int dst = ld_idx(ei2, (long long)NE2 + e, is64);
        float4 q = Q4[(size_t)dst * 32 + lane];
        float4 k = K4[(size_t)mid * 32 + lane];
        float p = q.x*k.x + q.y*k.y + q.z*k.z + q.w*k.w;
        #pragma unroll
        for (int off = 16; off; off >>= 1)
            p += __shfl_xor_sync(0xffffffffu, p, off);
        float ev = expf(p * INV_SQRT_C);
        if (lane == 0) { g_esc[e] = ev; wsum += ev; }
    }
    if (lane == 0) atomicAdd(&g_sum[0], wsum);
}

// ---------------- final scatter (x4 unrolled; inv inlined) -------------------
__global__ void __launch_bounds__(256) scatter2_kernel(const void* ei2, float* out) {
    const int is64 = g_idx64;
    const float inv = 1.0f / g_sum[0];
    const int lane = threadIdx.x & 31;
    const int warp  = (blockIdx.x * blockDim.x + threadIdx.x) >> 5;
    const int nwarp = (gridDim.x * blockDim.x) >> 5;
    const float4* V4 = (const float4*)g_V;
    int e = warp;
    for (; e + 3 * nwarp < NE2; e += 4 * nwarp) {
        int m[4], d[4];
        float a[4];
        #pragma unroll
        for (int j = 0; j < 4; j++) {
            m[j] = ld_idx(ei2, e + j * nwarp, is64);
            d[j] = ld_idx(ei2, (long long)NE2 + e + j * nwarp, is64);
            a[j] = g_esc[e + j * nwarp] * inv;
        }
        float4 v[4];
        #pragma unroll
        for (int j = 0; j < 4; j++) v[j] = V4[(size_t)m[j] * 32 + lane];
        #pragma unroll
        for (int j = 0; j < 4; j++) {
            v[j].x *= a[j]; v[j].y *= a[j]; v[j].z *= a[j]; v[j].w *= a[j];
            red_add_v4(out + (size_t)d[j] * C + lane * 4, v[j]);
        }
    }
    for (; e < NE2; e += nwarp) {
        int mid = ld_idx(ei2, e, is64);
        int dst = ld_idx(ei2, (long long)NE2 + e, is64);
        float alpha = g_esc[e] * inv;
        float4 v = V4[(size_t)mid * 32 + lane];
        v.x *= alpha; v.y *= alpha; v.z *= alpha; v.w *= alpha;
        red_add_v4(out + (size_t)dst * C + lane * 4, v);
    }
}

// ---------------------------------------------------------------------------
extern "C" void kernel_launch(void* const* d_in, const int* in_sizes, int n_in,
                              void* d_out, int out_size) {
    const float* x_src = (const float*)d_in[0];
    const float* x_mid = (const float*)d_in[1];
    const float* x_dst = (const float*)d_in[2];
    const void*  ei1   = d_in[3];
    const void*  ei2   = d_in[4];
    const float* W1w   = (const float*)d_in[5];
    const float* W1b   = (const float*)d_in[6];
    const float* W2w   = (const float*)d_in[7];
    const float* W2b   = (const float*)d_in[8];
    const float* qw    = (const float*)d_in[9];
    const float* qb    = (const float*)d_in[10];
    const float* kw    = (const float*)d_in[11];
    const float* kb    = (const float*)d_in[12];
    const float* vw    = (const float*)d_in[13];
    const float* vb    = (const float*)d_in[14];
    float* out = (float*)d_out;

    float *p_h, *p_K, *p_V, *p_Q;
    cudaGetSymbolAddress((void**)&p_h, g_h);
    cudaGetSymbolAddress((void**)&p_K, g_K);
    cudaGetSymbolAddress((void**)&p_V, g_V);
    cudaGetSymbolAddress((void**)&p_Q, g_Q);

    cudaFuncSetAttribute(gemm_mma_kernel,
                         cudaFuncAttributeMaxDynamicSharedMemorySize, SMG_BYTES);
    cudaFuncSetAttribute(gemmh_mma_kernel,
                         cudaFuncAttributeMaxDynamicSharedMemorySize, SMH_BYTES);
    cudaFuncSetAttribute(gemm_kv_kernel,
                         cudaFuncAttributeMaxDynamicSharedMemorySize, SMKV_BYTES);

    zero_all_kernel<<<1024, 256>>>((float4*)out);
    detect_kernel<<<1, 1>>>(ei1);

    // stage 1: scatter raw features + degrees, then dense h GEMM (HMMA)
    scatter1_kernel<<<1184, 256>>>(ei1, x_src);
    gemmh_mma_kernel<<<148, 256, SMH_BYTES>>>(x_mid, W1w, W1b, W2w, W2b);

    // stage 2: fused K+V GEMM on h; Q GEMM on x_dst (HMMA)
    gemm_kv_kernel<<<148, 256, SMKV_BYTES>>>(p_h, kw, kb, p_K, vw, vb, p_V, NM);
    gemm_mma_kernel<<<148, 256, SMG_BYTES>>>(x_dst, qw, qb, p_Q, ND);

    // edge scores -> global softmax -> weighted scatter
    score_kernel<<<1184, 256>>>(ei2);
    scatter2_kernel<<<1184, 256>>>(ei2, out);
}